// round 2
// baseline (speedup 1.0000x reference)
#include <cuda_runtime.h>

#define NN 50000
#define EE 800000
#define CC 64
#define BN_EPS 1e-5f

// ---------------- scratch (static device arrays; no allocation) -------------
__device__ float    g_c1[NN];          // sum_e s_e      per src node
__device__ float    g_c2[NN];          // sum_e s_e^2    per src node
__device__ int      g_cnt[NN];         // in-degree per dst node
__device__ int      g_start[NN + 1];   // CSR row starts
__device__ int      g_cursor[NN];      // fill cursors
__device__ uint2    g_epack[EE];       // (src, bits(s_e)) bucketed by dst
__device__ float    g_S1[CC];
__device__ float    g_S2[CC];
__device__ float    g_alpha[CC];
__device__ float    g_delta[CC];
__device__ float    g_hsum[CC];
__device__ float    g_hsq[CC];
__device__ float    g_a2[CC];
__device__ float    g_b2[CC];
__device__ float    g_Y[NN * CC];      // X @ pool_W
__device__ float    g_aggf[NN * CC];   // scatter-max result
__device__ float    g_h[NN * CC];      // pre-BN final features

// ---------------- K0: zero the small per-replay state -----------------------
__global__ void k0_zero() {
    int i = blockIdx.x * blockDim.x + threadIdx.x;
    int stride = gridDim.x * blockDim.x;
    for (int idx = i; idx < NN; idx += stride) {
        g_c1[idx] = 0.f; g_c2[idx] = 0.f; g_cnt[idx] = 0;
    }
    if (i < CC) { g_S1[i] = 0.f; g_S2[i] = 0.f; g_hsum[i] = 0.f; g_hsq[i] = 0.f; }
}

// ---------------- K1: per-src sums of s, s^2 + per-dst counts ----------------
__global__ void k1_edge_stats(const int* __restrict__ ei,
                              const float* __restrict__ ew,
                              const float* __restrict__ coefp) {
    int e = blockIdx.x * blockDim.x + threadIdx.x;
    if (e >= EE) return;
    float coef = __ldg(coefp);
    int src = ei[e];
    int dst = ei[EE + e];
    float s = fmaf(coef, ew[e], 1.0f);
    atomicAdd(&g_c1[src], s);
    atomicAdd(&g_c2[src], s * s);
    atomicAdd(&g_cnt[dst], 1);
}

// ---------------- K1b: single-block exclusive scan of counts -----------------
__global__ void k1b_scan() {
    __shared__ int sh[1024];
    int t = threadIdx.x;
    const int CH = (NN + 1023) / 1024;   // 49
    int base = t * CH;
    int sum = 0;
    for (int i = 0; i < CH; i++) {
        int idx = base + i;
        if (idx < NN) sum += g_cnt[idx];
    }
    sh[t] = sum;
    __syncthreads();
    for (int off = 1; off < 1024; off <<= 1) {
        int v = (t >= off) ? sh[t - off] : 0;
        __syncthreads();
        sh[t] += v;
        __syncthreads();
    }
    int run = sh[t] - sum;               // exclusive prefix
    for (int i = 0; i < CH; i++) {
        int idx = base + i;
        if (idx < NN) {
            g_start[idx] = run;
            g_cursor[idx] = run;
            run += g_cnt[idx];
        }
    }
    if (t == 0) g_start[NN] = EE;
}

// ---------------- K1c: bucket edges by dst -----------------------------------
__global__ void k1c_fill(const int* __restrict__ ei,
                         const float* __restrict__ ew,
                         const float* __restrict__ coefp) {
    int e = blockIdx.x * blockDim.x + threadIdx.x;
    if (e >= EE) return;
    float coef = __ldg(coefp);
    int src = ei[e];
    int dst = ei[EE + e];
    float s = fmaf(coef, ew[e], 1.0f);
    int pos = atomicAdd(&g_cursor[dst], 1);
    g_epack[pos] = make_uint2((unsigned)src, __float_as_uint(s));
}

// ---------------- K2: Y = X @ pool_W  (thread-per-row, W in smem) ------------
__global__ void __launch_bounds__(128) k2_xw(const float* __restrict__ x,
                                             const float* __restrict__ W) {
    __shared__ float Ws[CC * CC];
    for (int i = threadIdx.x; i < CC * CC; i += blockDim.x) Ws[i] = W[i];
    __syncthreads();
    int r = blockIdx.x * blockDim.x + threadIdx.x;
    if (r >= NN) return;
    float y[CC];
#pragma unroll
    for (int c = 0; c < CC; c++) y[c] = 0.f;
    const float4* xr = reinterpret_cast<const float4*>(x + (size_t)r * CC);
#pragma unroll
    for (int k4 = 0; k4 < 16; k4++) {
        float4 xv = xr[k4];
        const float* w0 = &Ws[(k4 * 4 + 0) * CC];
        const float* w1 = &Ws[(k4 * 4 + 1) * CC];
        const float* w2 = &Ws[(k4 * 4 + 2) * CC];
        const float* w3 = &Ws[(k4 * 4 + 3) * CC];
#pragma unroll
        for (int c = 0; c < CC; c += 4) {
            float4 a = *reinterpret_cast<const float4*>(w0 + c);
            float4 b = *reinterpret_cast<const float4*>(w1 + c);
            float4 d = *reinterpret_cast<const float4*>(w2 + c);
            float4 f = *reinterpret_cast<const float4*>(w3 + c);
            y[c + 0] += xv.x * a.x + xv.y * b.x + xv.z * d.x + xv.w * f.x;
            y[c + 1] += xv.x * a.y + xv.y * b.y + xv.z * d.y + xv.w * f.y;
            y[c + 2] += xv.x * a.z + xv.y * b.z + xv.z * d.z + xv.w * f.z;
            y[c + 3] += xv.x * a.w + xv.y * b.w + xv.z * d.w + xv.w * f.w;
        }
    }
    float4* yr = reinterpret_cast<float4*>(g_Y + (size_t)r * CC);
#pragma unroll
    for (int c4 = 0; c4 < 16; c4++) {
        float4 v;
        v.x = y[c4 * 4 + 0]; v.y = y[c4 * 4 + 1];
        v.z = y[c4 * 4 + 2]; v.w = y[c4 * 4 + 3];
        yr[c4] = v;
    }
}

// ---------------- K2b: S1_c = sum c1*Y, S2_c = sum c2*Y^2 --------------------
// block = 256 (8 row-groups of 32 threads; each thread owns a channel pair)
__global__ void __launch_bounds__(256) k2b_reduce_Y() {
    int cp  = threadIdx.x & 31;       // channel pair 0..31
    int grp = threadIdx.x >> 5;       // 0..7
    float s1x = 0.f, s1y = 0.f, s2x = 0.f, s2y = 0.f;
    for (int r = blockIdx.x * 8 + grp; r < NN; r += gridDim.x * 8) {
        float c1v = g_c1[r], c2v = g_c2[r];
        float2 y = *reinterpret_cast<const float2*>(g_Y + (size_t)r * CC + 2 * cp);
        s1x += c1v * y.x; s1y += c1v * y.y;
        s2x += c2v * y.x * y.x; s2y += c2v * y.y * y.y;
    }
    __shared__ float sm[4][8][32];
    sm[0][grp][cp] = s1x; sm[1][grp][cp] = s1y;
    sm[2][grp][cp] = s2x; sm[3][grp][cp] = s2y;
    __syncthreads();
    if (grp < 4) {
        float a = 0.f;
#pragma unroll
        for (int j = 0; j < 8; j++) a += sm[grp][j][cp];
        float* tgt = (grp < 2) ? g_S1 : g_S2;
        atomicAdd(&tgt[2 * cp + (grp & 1)], a);
    }
}

// ---------------- K3: pool-BN coefficients ------------------------------------
__global__ void k3_pool_coeffs(const float* __restrict__ pb,
                               const float* __restrict__ gamma,
                               const float* __restrict__ beta) {
    int c = threadIdx.x;
    float invE = 1.0f / (float)EE;
    float b = pb[c];
    float mean = g_S1[c] * invE + b;
    float msq = (g_S2[c] + 2.f * b * g_S1[c]) * invE + b * b;
    float var = msq - mean * mean;
    float alpha = gamma[c] * rsqrtf(var + BN_EPS);
    g_alpha[c] = alpha;
    g_delta[c] = beta[c] + alpha * (b - mean);
}

// ---------------- K4: warp-per-node CSR max-reduce (no atomics) ---------------
__global__ void __launch_bounds__(256) k4_compute() {
    int gwarp = (blockIdx.x * blockDim.x + threadIdx.x) >> 5;
    if (gwarp >= NN) return;
    int lane = threadIdx.x & 31;
    float a0 = g_alpha[2 * lane], a1 = g_alpha[2 * lane + 1];
    float d0 = g_delta[2 * lane], d1 = g_delta[2 * lane + 1];
    int j0 = g_start[gwarp], j1 = g_start[gwarp + 1];
    float m0 = 0.f, m1 = 0.f;
    if (j0 < j1) {
        uint2 p = g_epack[j0];
        for (int j = j0; j < j1; j++) {
            uint2 pn;
            if (j + 1 < j1) pn = g_epack[j + 1];
            float s = __uint_as_float(p.y);
            float2 yv = *reinterpret_cast<const float2*>(
                g_Y + (size_t)p.x * CC + 2 * lane);
            m0 = fmaxf(m0, fmaf(a0 * s, yv.x, d0));
            m1 = fmaxf(m1, fmaf(a1 * s, yv.y, d1));
            p = pn;
        }
    }
    *reinterpret_cast<float2*>(g_aggf + (size_t)gwarp * CC + 2 * lane) =
        make_float2(m0, m1);
}

// ---------------- K5: h = [x, agg] @ final_W + final_b ------------------------
__global__ void __launch_bounds__(128) k5_final(const float* __restrict__ x,
                                                const float* __restrict__ Wf,
                                                const float* __restrict__ fb) {
    __shared__ float Ws[128 * CC];   // 32 KB
    for (int i = threadIdx.x; i < 128 * CC; i += blockDim.x) Ws[i] = Wf[i];
    __syncthreads();
    int r = blockIdx.x * blockDim.x + threadIdx.x;
    if (r >= NN) return;
    float h[CC];
#pragma unroll
    for (int c = 0; c < CC; c++) h[c] = __ldg(fb + c);

    const float4* xr = reinterpret_cast<const float4*>(x + (size_t)r * CC);
    const float4* ar = reinterpret_cast<const float4*>(g_aggf + (size_t)r * CC);
#pragma unroll
    for (int half = 0; half < 2; half++) {
        const float4* src4 = (half == 0) ? xr : ar;
        const float* Wbase = &Ws[half * 64 * CC];
#pragma unroll
        for (int k4 = 0; k4 < 16; k4++) {
            float4 xv = src4[k4];
            const float* w0 = Wbase + (k4 * 4 + 0) * CC;
            const float* w1 = Wbase + (k4 * 4 + 1) * CC;
            const float* w2 = Wbase + (k4 * 4 + 2) * CC;
            const float* w3 = Wbase + (k4 * 4 + 3) * CC;
#pragma unroll
            for (int c = 0; c < CC; c += 4) {
                float4 a = *reinterpret_cast<const float4*>(w0 + c);
                float4 b = *reinterpret_cast<const float4*>(w1 + c);
                float4 d = *reinterpret_cast<const float4*>(w2 + c);
                float4 f = *reinterpret_cast<const float4*>(w3 + c);
                h[c + 0] += xv.x * a.x + xv.y * b.x + xv.z * d.x + xv.w * f.x;
                h[c + 1] += xv.x * a.y + xv.y * b.y + xv.z * d.y + xv.w * f.y;
                h[c + 2] += xv.x * a.z + xv.y * b.z + xv.z * d.z + xv.w * f.z;
                h[c + 3] += xv.x * a.w + xv.y * b.w + xv.z * d.w + xv.w * f.w;
            }
        }
    }
    float4* hr = reinterpret_cast<float4*>(g_h + (size_t)r * CC);
#pragma unroll
    for (int c4 = 0; c4 < 16; c4++) {
        float4 v;
        v.x = h[c4 * 4 + 0]; v.y = h[c4 * 4 + 1];
        v.z = h[c4 * 4 + 2]; v.w = h[c4 * 4 + 3];
        hr[c4] = v;
    }
}

// ---------------- K5b: per-channel sum/sumsq of h -----------------------------
__global__ void __launch_bounds__(256) k5b_reduce_h() {
    int cp  = threadIdx.x & 31;
    int grp = threadIdx.x >> 5;
    float s1x = 0.f, s1y = 0.f, s2x = 0.f, s2y = 0.f;
    for (int r = blockIdx.x * 8 + grp; r < NN; r += gridDim.x * 8) {
        float2 y = *reinterpret_cast<const float2*>(g_h + (size_t)r * CC + 2 * cp);
        s1x += y.x; s1y += y.y;
        s2x += y.x * y.x; s2y += y.y * y.y;
    }
    __shared__ float sm[4][8][32];
    sm[0][grp][cp] = s1x; sm[1][grp][cp] = s1y;
    sm[2][grp][cp] = s2x; sm[3][grp][cp] = s2y;
    __syncthreads();
    if (grp < 4) {
        float a = 0.f;
#pragma unroll
        for (int j = 0; j < 8; j++) a += sm[grp][j][cp];
        float* tgt = (grp < 2) ? g_hsum : g_hsq;
        atomicAdd(&tgt[2 * cp + (grp & 1)], a);
    }
}

// ---------------- K6: final-BN coefficients -----------------------------------
__global__ void k6_final_coeffs(const float* __restrict__ gamma,
                                const float* __restrict__ beta) {
    int c = threadIdx.x;
    float invN = 1.0f / (float)NN;
    float mean = g_hsum[c] * invN;
    float var = g_hsq[c] * invN - mean * mean;
    float a = gamma[c] * rsqrtf(var + BN_EPS);
    g_a2[c] = a;
    g_b2[c] = beta[c] - a * mean;
}

// ---------------- K7: out = relu(a2*h + b2) -----------------------------------
__global__ void k7_epilogue(float* __restrict__ out) {
    int i = blockIdx.x * blockDim.x + threadIdx.x;
    int stride = gridDim.x * blockDim.x;
    const float4* hv = reinterpret_cast<const float4*>(g_h);
    float4* ov = reinterpret_cast<float4*>(out);
    for (int q = i; q < NN * 16; q += stride) {
        int c4 = (q & 15) * 4;
        float4 h = hv[q];
        float4 r;
        r.x = fmaxf(0.f, fmaf(g_a2[c4 + 0], h.x, g_b2[c4 + 0]));
        r.y = fmaxf(0.f, fmaf(g_a2[c4 + 1], h.y, g_b2[c4 + 1]));
        r.z = fmaxf(0.f, fmaf(g_a2[c4 + 2], h.z, g_b2[c4 + 2]));
        r.w = fmaxf(0.f, fmaf(g_a2[c4 + 3], h.w, g_b2[c4 + 3]));
        ov[q] = r;
    }
}

// ---------------- launch -------------------------------------------------------
extern "C" void kernel_launch(void* const* d_in, const int* in_sizes, int n_in,
                              void* d_out, int out_size) {
    const float* x     = (const float*)d_in[0];
    const int*   ei    = (const int*)d_in[1];
    const float* ew    = (const float*)d_in[2];
    const float* pW    = (const float*)d_in[3];
    const float* pb    = (const float*)d_in[4];
    const float* pg    = (const float*)d_in[5];
    const float* pbeta = (const float*)d_in[6];
    const float* fW    = (const float*)d_in[7];
    const float* fb    = (const float*)d_in[8];
    const float* fg    = (const float*)d_in[9];
    const float* fbeta = (const float*)d_in[10];
    const float* coef  = (const float*)d_in[11];
    float* out = (float*)d_out;

    k0_zero<<<256, 256>>>();
    k1_edge_stats<<<(EE + 255) / 256, 256>>>(ei, ew, coef);
    k1b_scan<<<1, 1024>>>();
    k1c_fill<<<(EE + 255) / 256, 256>>>(ei, ew, coef);
    k2_xw<<<(NN + 127) / 128, 128>>>(x, pW);
    k2b_reduce_Y<<<1184, 256>>>();
    k3_pool_coeffs<<<1, 64>>>(pb, pg, pbeta);
    k4_compute<<<(NN * 32 + 255) / 256, 256>>>();
    k5_final<<<(NN + 127) / 128, 128>>>(x, fW, fb);
    k5b_reduce_h<<<1184, 256>>>();
    k6_final_coeffs<<<1, 64>>>(fg, fbeta);
    k7_epilogue<<<1024, 256>>>(out);
}

// round 3
// speedup vs baseline: 1.4459x; 1.4459x over previous
#include <cuda_runtime.h>

#define NN 50000
#define EE 800000
#define CC 64
#define BN_EPS 1e-5f

// ---------------- scratch (static device arrays; no allocation) -------------
__device__ float    g_c1[NN];        // sum_e s_e        per src node
__device__ float    g_c2[NN];        // sum_e s_e^2      per src node
__device__ float    g_S1[CC];
__device__ float    g_S2[CC];
__device__ float    g_alpha[CC];
__device__ float    g_delta[CC];
__device__ float    g_hsum[CC];
__device__ float    g_hsq[CC];
__device__ float    g_a2[CC];
__device__ float    g_b2[CC];
__device__ float    g_Y[NN * CC];    // X @ pool_W
__device__ float    g_aggf[NN * CC]; // scatter-max result (>= 0)

// ---------------- K0: zero per-replay state ----------------------------------
__global__ void k0_zero() {
    int i = blockIdx.x * blockDim.x + threadIdx.x;
    int stride = gridDim.x * blockDim.x;
    float4 z = make_float4(0.f, 0.f, 0.f, 0.f);
    float4* a4 = reinterpret_cast<float4*>(g_aggf);
    for (int idx = i; idx < NN * CC / 4; idx += stride) a4[idx] = z;
    for (int idx = i; idx < NN; idx += stride) { g_c1[idx] = 0.f; g_c2[idx] = 0.f; }
    if (i < CC) { g_S1[i] = 0.f; g_S2[i] = 0.f; g_hsum[i] = 0.f; g_hsq[i] = 0.f; }
}

// ---------------- K1: per-src sums of s, s^2 ----------------------------------
__global__ void k1_edge_stats(const int* __restrict__ ei,
                              const float* __restrict__ ew,
                              const float* __restrict__ coefp) {
    int e = blockIdx.x * blockDim.x + threadIdx.x;
    if (e >= EE) return;
    float coef = __ldg(coefp);
    int src = ei[e];
    float s = fmaf(coef, ew[e], 1.0f);
    atomicAdd(&g_c1[src], s);
    atomicAdd(&g_c2[src], s * s);
}

// ---------------- K2: Y = X @ pool_W  (thread-per-row, W in smem) -------------
__global__ void __launch_bounds__(128) k2_xw(const float* __restrict__ x,
                                             const float* __restrict__ W) {
    __shared__ float Ws[CC * CC];
    for (int i = threadIdx.x; i < CC * CC; i += blockDim.x) Ws[i] = W[i];
    __syncthreads();
    int r = blockIdx.x * blockDim.x + threadIdx.x;
    if (r >= NN) return;
    float y[CC];
#pragma unroll
    for (int c = 0; c < CC; c++) y[c] = 0.f;
    const float4* xr = reinterpret_cast<const float4*>(x + (size_t)r * CC);
#pragma unroll
    for (int k4 = 0; k4 < 16; k4++) {
        float4 xv = xr[k4];
        const float* w0 = &Ws[(k4 * 4 + 0) * CC];
        const float* w1 = &Ws[(k4 * 4 + 1) * CC];
        const float* w2 = &Ws[(k4 * 4 + 2) * CC];
        const float* w3 = &Ws[(k4 * 4 + 3) * CC];
#pragma unroll
        for (int c = 0; c < CC; c += 4) {
            float4 a = *reinterpret_cast<const float4*>(w0 + c);
            float4 b = *reinterpret_cast<const float4*>(w1 + c);
            float4 d = *reinterpret_cast<const float4*>(w2 + c);
            float4 f = *reinterpret_cast<const float4*>(w3 + c);
            y[c + 0] += xv.x * a.x + xv.y * b.x + xv.z * d.x + xv.w * f.x;
            y[c + 1] += xv.x * a.y + xv.y * b.y + xv.z * d.y + xv.w * f.y;
            y[c + 2] += xv.x * a.z + xv.y * b.z + xv.z * d.z + xv.w * f.z;
            y[c + 3] += xv.x * a.w + xv.y * b.w + xv.z * d.w + xv.w * f.w;
        }
    }
    float4* yr = reinterpret_cast<float4*>(g_Y + (size_t)r * CC);
#pragma unroll
    for (int c4 = 0; c4 < 16; c4++) {
        float4 v;
        v.x = y[c4 * 4 + 0]; v.y = y[c4 * 4 + 1];
        v.z = y[c4 * 4 + 2]; v.w = y[c4 * 4 + 3];
        yr[c4] = v;
    }
}

// ---------------- K2b: S1_c = sum c1*Y, S2_c = sum c2*Y^2 ---------------------
__global__ void __launch_bounds__(256) k2b_reduce_Y() {
    int cp  = threadIdx.x & 31;       // channel pair 0..31
    int grp = threadIdx.x >> 5;       // 0..7
    float s1x = 0.f, s1y = 0.f, s2x = 0.f, s2y = 0.f;
    for (int r = blockIdx.x * 8 + grp; r < NN; r += gridDim.x * 8) {
        float c1v = g_c1[r], c2v = g_c2[r];
        float2 y = *reinterpret_cast<const float2*>(g_Y + (size_t)r * CC + 2 * cp);
        s1x += c1v * y.x; s1y += c1v * y.y;
        s2x += c2v * y.x * y.x; s2y += c2v * y.y * y.y;
    }
    __shared__ float sm[4][8][32];
    sm[0][grp][cp] = s1x; sm[1][grp][cp] = s1y;
    sm[2][grp][cp] = s2x; sm[3][grp][cp] = s2y;
    __syncthreads();
    if (grp < 4) {
        float a = 0.f;
#pragma unroll
        for (int j = 0; j < 8; j++) a += sm[grp][j][cp];
        float* tgt = (grp < 2) ? g_S1 : g_S2;
        atomicAdd(&tgt[2 * cp + (grp & 1)], a);
    }
}

// ---------------- K3: pool-BN coefficients ------------------------------------
__global__ void k3_pool_coeffs(const float* __restrict__ pb,
                               const float* __restrict__ gamma,
                               const float* __restrict__ beta) {
    int c = threadIdx.x;
    float invE = 1.0f / (float)EE;
    float b = pb[c];
    float mean = g_S1[c] * invE + b;
    float msq = (g_S2[c] + 2.f * b * g_S1[c]) * invE + b * b;
    float var = msq - mean * mean;
    float alpha = gamma[c] * rsqrtf(var + BN_EPS);
    g_alpha[c] = alpha;
    g_delta[c] = beta[c] + alpha * (b - mean);
}

// ---------------- K4: filtered scatter-max -------------------------------------
// Plain-load the current agg value first; only atomicMax when strictly greater.
// Safe: agg is monotone non-decreasing from 0, so any observed (even stale)
// value is a lower bound of the final max.
__global__ void __launch_bounds__(256) k4_scatter(const int* __restrict__ ei,
                                                  const float* __restrict__ ew,
                                                  const float* __restrict__ coefp) {
    float coef = __ldg(coefp);
    int lane = threadIdx.x & 31;
    int warp = (blockIdx.x * blockDim.x + threadIdx.x) >> 5;
    int nwarps = (gridDim.x * blockDim.x) >> 5;
    float al0 = g_alpha[2 * lane],     al1 = g_alpha[2 * lane + 1];
    float de0 = g_delta[2 * lane],     de1 = g_delta[2 * lane + 1];
    for (int base = warp * 32; base < EE; base += nwarps * 32) {
        int e = base + lane;
        int src = 0, dst = 0; float s = 0.f;
        if (e < EE) {
            src = ei[e];
            dst = ei[EE + e];
            s = fmaf(coef, ew[e], 1.0f);
        }
        int cnt = min(32, EE - base);
        for (int i = 0; i < cnt; i++) {
            int   sI = __shfl_sync(0xffffffffu, src, i);
            int   dI = __shfl_sync(0xffffffffu, dst, i);
            float sS = __shfl_sync(0xffffffffu, s, i);
            float2 yv = *reinterpret_cast<const float2*>(
                g_Y + (size_t)sI * CC + 2 * lane);
            float v0 = fmaf(al0 * sS, yv.x, de0);
            float v1 = fmaf(al1 * sS, yv.y, de1);
            float* arow = g_aggf + (size_t)dI * CC + 2 * lane;
            float2 cur = *reinterpret_cast<const float2*>(arow);
            if (v0 > cur.x)
                atomicMax(reinterpret_cast<unsigned*>(arow),     __float_as_uint(v0));
            if (v1 > cur.y)
                atomicMax(reinterpret_cast<unsigned*>(arow) + 1, __float_as_uint(v1));
        }
    }
}

// ---------------- K5: h = [x, agg] @ final_W + final_b  (writes d_out) --------
__global__ void __launch_bounds__(128) k5_final(const float* __restrict__ x,
                                                const float* __restrict__ Wf,
                                                const float* __restrict__ fb,
                                                float* __restrict__ hout) {
    __shared__ float Ws[128 * CC];   // 32 KB
    for (int i = threadIdx.x; i < 128 * CC; i += blockDim.x) Ws[i] = Wf[i];
    __syncthreads();
    int r = blockIdx.x * blockDim.x + threadIdx.x;
    if (r >= NN) return;
    float h[CC];
#pragma unroll
    for (int c = 0; c < CC; c++) h[c] = __ldg(fb + c);

    const float4* xr = reinterpret_cast<const float4*>(x + (size_t)r * CC);
    const float4* ar = reinterpret_cast<const float4*>(g_aggf + (size_t)r * CC);
#pragma unroll
    for (int half = 0; half < 2; half++) {
        const float4* src4 = (half == 0) ? xr : ar;
        const float* Wbase = &Ws[half * 64 * CC];
#pragma unroll
        for (int k4 = 0; k4 < 16; k4++) {
            float4 xv = src4[k4];
            const float* w0 = Wbase + (k4 * 4 + 0) * CC;
            const float* w1 = Wbase + (k4 * 4 + 1) * CC;
            const float* w2 = Wbase + (k4 * 4 + 2) * CC;
            const float* w3 = Wbase + (k4 * 4 + 3) * CC;
#pragma unroll
            for (int c = 0; c < CC; c += 4) {
                float4 a = *reinterpret_cast<const float4*>(w0 + c);
                float4 b = *reinterpret_cast<const float4*>(w1 + c);
                float4 d = *reinterpret_cast<const float4*>(w2 + c);
                float4 f = *reinterpret_cast<const float4*>(w3 + c);
                h[c + 0] += xv.x * a.x + xv.y * b.x + xv.z * d.x + xv.w * f.x;
                h[c + 1] += xv.x * a.y + xv.y * b.y + xv.z * d.y + xv.w * f.y;
                h[c + 2] += xv.x * a.z + xv.y * b.z + xv.z * d.z + xv.w * f.z;
                h[c + 3] += xv.x * a.w + xv.y * b.w + xv.z * d.w + xv.w * f.w;
            }
        }
    }
    float4* hr = reinterpret_cast<float4*>(hout + (size_t)r * CC);
#pragma unroll
    for (int c4 = 0; c4 < 16; c4++) {
        float4 v;
        v.x = h[c4 * 4 + 0]; v.y = h[c4 * 4 + 1];
        v.z = h[c4 * 4 + 2]; v.w = h[c4 * 4 + 3];
        hr[c4] = v;
    }
}

// ---------------- K5b: per-channel sum/sumsq of h (reads d_out) ----------------
__global__ void __launch_bounds__(256) k5b_reduce_h(const float* __restrict__ h) {
    int cp  = threadIdx.x & 31;
    int grp = threadIdx.x >> 5;
    float s1x = 0.f, s1y = 0.f, s2x = 0.f, s2y = 0.f;
    for (int r = blockIdx.x * 8 + grp; r < NN; r += gridDim.x * 8) {
        float2 y = *reinterpret_cast<const float2*>(h + (size_t)r * CC + 2 * cp);
        s1x += y.x; s1y += y.y;
        s2x += y.x * y.x; s2y += y.y * y.y;
    }
    __shared__ float sm[4][8][32];
    sm[0][grp][cp] = s1x; sm[1][grp][cp] = s1y;
    sm[2][grp][cp] = s2x; sm[3][grp][cp] = s2y;
    __syncthreads();
    if (grp < 4) {
        float a = 0.f;
#pragma unroll
        for (int j = 0; j < 8; j++) a += sm[grp][j][cp];
        float* tgt = (grp < 2) ? g_hsum : g_hsq;
        atomicAdd(&tgt[2 * cp + (grp & 1)], a);
    }
}

// ---------------- K6: final-BN coefficients ------------------------------------
__global__ void k6_final_coeffs(const float* __restrict__ gamma,
                                const float* __restrict__ beta) {
    int c = threadIdx.x;
    float invN = 1.0f / (float)NN;
    float mean = g_hsum[c] * invN;
    float var = g_hsq[c] * invN - mean * mean;
    float a = gamma[c] * rsqrtf(var + BN_EPS);
    g_a2[c] = a;
    g_b2[c] = beta[c] - a * mean;
}

// ---------------- K7: out = relu(a2*out + b2), in place -------------------------
__global__ void k7_epilogue(float* __restrict__ out) {
    int i = blockIdx.x * blockDim.x + threadIdx.x;
    int stride = gridDim.x * blockDim.x;
    float4* ov = reinterpret_cast<float4*>(out);
    for (int q = i; q < NN * 16; q += stride) {
        int c4 = (q & 15) * 4;
        float4 h = ov[q];
        float4 r;
        r.x = fmaxf(0.f, fmaf(g_a2[c4 + 0], h.x, g_b2[c4 + 0]));
        r.y = fmaxf(0.f, fmaf(g_a2[c4 + 1], h.y, g_b2[c4 + 1]));
        r.z = fmaxf(0.f, fmaf(g_a2[c4 + 2], h.z, g_b2[c4 + 2]));
        r.w = fmaxf(0.f, fmaf(g_a2[c4 + 3], h.w, g_b2[c4 + 3]));
        ov[q] = r;
    }
}

// ---------------- launch ---------------------------------------------------------
extern "C" void kernel_launch(void* const* d_in, const int* in_sizes, int n_in,
                              void* d_out, int out_size) {
    const float* x     = (const float*)d_in[0];
    const int*   ei    = (const int*)d_in[1];
    const float* ew    = (const float*)d_in[2];
    const float* pW    = (const float*)d_in[3];
    const float* pb    = (const float*)d_in[4];
    const float* pg    = (const float*)d_in[5];
    const float* pbeta = (const float*)d_in[6];
    const float* fW    = (const float*)d_in[7];
    const float* fb    = (const float*)d_in[8];
    const float* fg    = (const float*)d_in[9];
    const float* fbeta = (const float*)d_in[10];
    const float* coef  = (const float*)d_in[11];
    float* out = (float*)d_out;

    k0_zero<<<1024, 256>>>();
    k1_edge_stats<<<(EE + 255) / 256, 256>>>(ei, ew, coef);
    k2_xw<<<(NN + 127) / 128, 128>>>(x, pW);
    k2b_reduce_Y<<<1184, 256>>>();
    k3_pool_coeffs<<<1, 64>>>(pb, pg, pbeta);
    k4_scatter<<<592, 256>>>(ei, ew, coef);
    k5_final<<<(NN + 127) / 128, 128>>>(x, fW, fb, out);
    k5b_reduce_h<<<1184, 256>>>(out);
    k6_final_coeffs<<<1, 64>>>(fg, fbeta);
    k7_epilogue<<<1024, 256>>>(out);
}

// round 4
// speedup vs baseline: 1.6506x; 1.1416x over previous
#include <cuda_runtime.h>

#define NN 50000
#define EE 800000
#define CC 64
#define BN_EPS 1e-5f

// ---------------- packed f32x2 helpers (Blackwell sm_103a) -------------------
#define PACK_DUP2(out, f) \
    asm("mov.b64 %0, {%1, %1};" : "=l"(out) : "r"(__float_as_uint(f)))
#define PACK2(out, f0, f1) \
    asm("mov.b64 %0, {%1, %2};" : "=l"(out) : "r"(__float_as_uint(f0)), "r"(__float_as_uint(f1)))
#define FMA2(d, a, b) \
    asm("fma.rn.f32x2 %0, %1, %2, %0;" : "+l"(d) : "l"(a), "l"(b))
#define UNPACK2(lo, hi, v) \
    asm("mov.b64 {%0, %1}, %2;" : "=r"(lo), "=r"(hi) : "l"(v))

// ---------------- scratch (static device arrays; no allocation) -------------
__device__ float2   g_cs[NN];        // (sum s, sum s^2) per src node
__device__ float    g_S1[CC];
__device__ float    g_S2[CC];
__device__ float    g_alpha[CC];
__device__ float    g_delta[CC];
__device__ float    g_hsum[CC];
__device__ float    g_hsq[CC];
__device__ float    g_a2[CC];
__device__ float    g_b2[CC];
__device__ float    g_Y[NN * CC];    // X @ pool_W
__device__ float    g_aggf[NN * CC]; // scatter-max result (>= 0)

// ---------------- K0: zero per-replay state ----------------------------------
__global__ void k0_zero() {
    int i = blockIdx.x * blockDim.x + threadIdx.x;
    int stride = gridDim.x * blockDim.x;
    float4 z = make_float4(0.f, 0.f, 0.f, 0.f);
    float4* a4 = reinterpret_cast<float4*>(g_aggf);
    for (int idx = i; idx < NN * CC / 4; idx += stride) a4[idx] = z;
    for (int idx = i; idx < NN; idx += stride) g_cs[idx] = make_float2(0.f, 0.f);
    if (i < CC) { g_S1[i] = 0.f; g_S2[i] = 0.f; g_hsum[i] = 0.f; g_hsq[i] = 0.f; }
}

// ---------------- K1: per-src sums of s, s^2 ----------------------------------
__global__ void k1_edge_stats(const int* __restrict__ ei,
                              const float* __restrict__ ew,
                              const float* __restrict__ coefp) {
    int e = blockIdx.x * blockDim.x + threadIdx.x;
    if (e >= EE) return;
    float coef = __ldg(coefp);
    int src = ei[e];
    float s = fmaf(coef, ew[e], 1.0f);
    atomicAdd(&g_cs[src].x, s);
    atomicAdd(&g_cs[src].y, s * s);
}

// ---------------- K2: Y = X @ pool_W  (f32x2, 4 rows x 32 cols / thread) -----
// Block = 64 threads (2 warps). Block b: warp w handles column-half w of rows
// [b*128 + lane + 32j], j=0..3 — all gmem streams coalesced.
__global__ void __launch_bounds__(64) k2_xw(const float* __restrict__ x,
                                            const float* __restrict__ W) {
    __shared__ float Ws[CC * CC];   // 16 KB
    for (int i = threadIdx.x; i < CC * CC; i += 64) Ws[i] = W[i];
    __syncthreads();
    int half = threadIdx.x >> 5;
    int lane = threadIdx.x & 31;
    int rbase = blockIdx.x * 128 + lane;
    int r[4]; bool ok[4];
#pragma unroll
    for (int j = 0; j < 4; j++) { r[j] = rbase + 32 * j; ok[j] = r[j] < NN; }

    unsigned long long acc[4][16];
#pragma unroll
    for (int j = 0; j < 4; j++)
#pragma unroll
        for (int p = 0; p < 16; p++) acc[j][p] = 0ull;

    const float4 z4 = make_float4(0.f, 0.f, 0.f, 0.f);
#pragma unroll 4
    for (int k4 = 0; k4 < 16; k4++) {
        float4 xv[4];
#pragma unroll
        for (int j = 0; j < 4; j++)
            xv[j] = ok[j] ? *reinterpret_cast<const float4*>(
                                x + (size_t)r[j] * CC + k4 * 4)
                          : z4;
        float xk[4][4];
#pragma unroll
        for (int j = 0; j < 4; j++) {
            xk[j][0] = xv[j].x; xk[j][1] = xv[j].y;
            xk[j][2] = xv[j].z; xk[j][3] = xv[j].w;
        }
#pragma unroll
        for (int kk = 0; kk < 4; kk++) {
            unsigned long long a[4];
#pragma unroll
            for (int j = 0; j < 4; j++) PACK_DUP2(a[j], xk[j][kk]);
            const ulonglong2* wr = reinterpret_cast<const ulonglong2*>(
                &Ws[(k4 * 4 + kk) * CC + half * 32]);
#pragma unroll
            for (int p = 0; p < 8; p++) {
                ulonglong2 w = wr[p];
#pragma unroll
                for (int j = 0; j < 4; j++) {
                    FMA2(acc[j][2 * p],     a[j], w.x);
                    FMA2(acc[j][2 * p + 1], a[j], w.y);
                }
            }
        }
    }
#pragma unroll
    for (int j = 0; j < 4; j++) {
        if (!ok[j]) continue;
        float* dst = g_Y + (size_t)r[j] * CC + half * 32;
#pragma unroll
        for (int q = 0; q < 8; q++) {
            unsigned u0, u1, u2, u3;
            UNPACK2(u0, u1, acc[j][2 * q]);
            UNPACK2(u2, u3, acc[j][2 * q + 1]);
            float4 v;
            v.x = __uint_as_float(u0); v.y = __uint_as_float(u1);
            v.z = __uint_as_float(u2); v.w = __uint_as_float(u3);
            *reinterpret_cast<float4*>(dst + q * 4) = v;
        }
    }
}

// ---------------- K2b: S1_c = sum c1*Y, S2_c = sum c2*Y^2 (single pass) ------
__global__ void __launch_bounds__(256) k2b_reduce_Y() {
    int cp  = threadIdx.x & 31;       // channel pair 0..31
    int grp = threadIdx.x >> 5;       // 0..7
    int r0 = blockIdx.x * 32 + grp * 4;
    float2 y[4], cs[4];
#pragma unroll
    for (int j = 0; j < 4; j++) {
        int rr = r0 + j;
        bool ok = rr < NN;
        cs[j] = ok ? g_cs[rr] : make_float2(0.f, 0.f);
        y[j]  = ok ? *reinterpret_cast<const float2*>(g_Y + (size_t)rr * CC + 2 * cp)
                   : make_float2(0.f, 0.f);
    }
    float s1x = 0.f, s1y = 0.f, s2x = 0.f, s2y = 0.f;
#pragma unroll
    for (int j = 0; j < 4; j++) {
        s1x += cs[j].x * y[j].x; s1y += cs[j].x * y[j].y;
        s2x += cs[j].y * y[j].x * y[j].x; s2y += cs[j].y * y[j].y * y[j].y;
    }
    __shared__ float sm[4][8][32];
    sm[0][grp][cp] = s1x; sm[1][grp][cp] = s1y;
    sm[2][grp][cp] = s2x; sm[3][grp][cp] = s2y;
    __syncthreads();
    if (grp < 4) {
        float a = 0.f;
#pragma unroll
        for (int j = 0; j < 8; j++) a += sm[grp][j][cp];
        float* tgt = (grp < 2) ? g_S1 : g_S2;
        atomicAdd(&tgt[2 * cp + (grp & 1)], a);
    }
}

// ---------------- K3: pool-BN coefficients ------------------------------------
__global__ void k3_pool_coeffs(const float* __restrict__ pb,
                               const float* __restrict__ gamma,
                               const float* __restrict__ beta) {
    int c = threadIdx.x;
    float invE = 1.0f / (float)EE;
    float b = pb[c];
    float mean = g_S1[c] * invE + b;
    float msq = (g_S2[c] + 2.f * b * g_S1[c]) * invE + b * b;
    float var = msq - mean * mean;
    float alpha = gamma[c] * rsqrtf(var + BN_EPS);
    g_alpha[c] = alpha;
    g_delta[c] = beta[c] + alpha * (b - mean);
}

// ---------------- K4: filtered scatter-max -------------------------------------
__global__ void __launch_bounds__(256) k4_scatter(const int* __restrict__ ei,
                                                  const float* __restrict__ ew,
                                                  const float* __restrict__ coefp) {
    float coef = __ldg(coefp);
    int lane = threadIdx.x & 31;
    int warp = (blockIdx.x * blockDim.x + threadIdx.x) >> 5;
    int nwarps = (gridDim.x * blockDim.x) >> 5;
    float al0 = g_alpha[2 * lane],     al1 = g_alpha[2 * lane + 1];
    float de0 = g_delta[2 * lane],     de1 = g_delta[2 * lane + 1];
    for (int base = warp * 32; base < EE; base += nwarps * 32) {
        int e = base + lane;
        int src = 0, dst = 0; float s = 0.f;
        if (e < EE) {
            src = ei[e];
            dst = ei[EE + e];
            s = fmaf(coef, ew[e], 1.0f);
        }
        int cnt = min(32, EE - base);
        if (cnt == 32) {
#pragma unroll 4
            for (int i = 0; i < 32; i++) {
                int   sI = __shfl_sync(0xffffffffu, src, i);
                int   dI = __shfl_sync(0xffffffffu, dst, i);
                float sS = __shfl_sync(0xffffffffu, s, i);
                float2 yv = *reinterpret_cast<const float2*>(
                    g_Y + (size_t)sI * CC + 2 * lane);
                float v0 = fmaf(al0 * sS, yv.x, de0);
                float v1 = fmaf(al1 * sS, yv.y, de1);
                float* arow = g_aggf + (size_t)dI * CC + 2 * lane;
                float2 cur = *reinterpret_cast<const float2*>(arow);
                if (v0 > cur.x)
                    atomicMax(reinterpret_cast<unsigned*>(arow),     __float_as_uint(v0));
                if (v1 > cur.y)
                    atomicMax(reinterpret_cast<unsigned*>(arow) + 1, __float_as_uint(v1));
            }
        } else {
            for (int i = 0; i < cnt; i++) {
                int   sI = __shfl_sync(0xffffffffu, src, i);
                int   dI = __shfl_sync(0xffffffffu, dst, i);
                float sS = __shfl_sync(0xffffffffu, s, i);
                float2 yv = *reinterpret_cast<const float2*>(
                    g_Y + (size_t)sI * CC + 2 * lane);
                float v0 = fmaf(al0 * sS, yv.x, de0);
                float v1 = fmaf(al1 * sS, yv.y, de1);
                float* arow = g_aggf + (size_t)dI * CC + 2 * lane;
                float2 cur = *reinterpret_cast<const float2*>(arow);
                if (v0 > cur.x)
                    atomicMax(reinterpret_cast<unsigned*>(arow),     __float_as_uint(v0));
                if (v1 > cur.y)
                    atomicMax(reinterpret_cast<unsigned*>(arow) + 1, __float_as_uint(v1));
            }
        }
    }
}

// ---------------- K5: h = [x, agg] @ final_W + final_b  (f32x2 tiled) ---------
__global__ void __launch_bounds__(64) k5_final(const float* __restrict__ x,
                                               const float* __restrict__ Wf,
                                               const float* __restrict__ fb,
                                               float* __restrict__ hout) {
    __shared__ float Ws[2 * CC * CC];   // 32 KB
    for (int i = threadIdx.x; i < 2 * CC * CC; i += 64) Ws[i] = Wf[i];
    __syncthreads();
    int half = threadIdx.x >> 5;
    int lane = threadIdx.x & 31;
    int rbase = blockIdx.x * 128 + lane;
    int r[4]; bool ok[4];
#pragma unroll
    for (int j = 0; j < 4; j++) { r[j] = rbase + 32 * j; ok[j] = r[j] < NN; }

    unsigned long long acc[4][16];
    {
        const float* fbh = fb + half * 32;
        unsigned long long binit[16];
#pragma unroll
        for (int p = 0; p < 16; p++) PACK2(binit[p], fbh[2 * p], fbh[2 * p + 1]);
#pragma unroll
        for (int j = 0; j < 4; j++)
#pragma unroll
            for (int p = 0; p < 16; p++) acc[j][p] = binit[p];
    }

    const float4 z4 = make_float4(0.f, 0.f, 0.f, 0.f);
#pragma unroll
    for (int ph = 0; ph < 2; ph++) {
        const float* src = (ph == 0) ? x : g_aggf;
        const float* Wb  = Ws + ph * CC * CC;
#pragma unroll 4
        for (int k4 = 0; k4 < 16; k4++) {
            float4 xv[4];
#pragma unroll
            for (int j = 0; j < 4; j++)
                xv[j] = ok[j] ? *reinterpret_cast<const float4*>(
                                    src + (size_t)r[j] * CC + k4 * 4)
                              : z4;
            float xk[4][4];
#pragma unroll
            for (int j = 0; j < 4; j++) {
                xk[j][0] = xv[j].x; xk[j][1] = xv[j].y;
                xk[j][2] = xv[j].z; xk[j][3] = xv[j].w;
            }
#pragma unroll
            for (int kk = 0; kk < 4; kk++) {
                unsigned long long a[4];
#pragma unroll
                for (int j = 0; j < 4; j++) PACK_DUP2(a[j], xk[j][kk]);
                const ulonglong2* wr = reinterpret_cast<const ulonglong2*>(
                    &Wb[(k4 * 4 + kk) * CC + half * 32]);
#pragma unroll
                for (int p = 0; p < 8; p++) {
                    ulonglong2 w = wr[p];
#pragma unroll
                    for (int j = 0; j < 4; j++) {
                        FMA2(acc[j][2 * p],     a[j], w.x);
                        FMA2(acc[j][2 * p + 1], a[j], w.y);
                    }
                }
            }
        }
    }
#pragma unroll
    for (int j = 0; j < 4; j++) {
        if (!ok[j]) continue;
        float* dst = hout + (size_t)r[j] * CC + half * 32;
#pragma unroll
        for (int q = 0; q < 8; q++) {
            unsigned u0, u1, u2, u3;
            UNPACK2(u0, u1, acc[j][2 * q]);
            UNPACK2(u2, u3, acc[j][2 * q + 1]);
            float4 v;
            v.x = __uint_as_float(u0); v.y = __uint_as_float(u1);
            v.z = __uint_as_float(u2); v.w = __uint_as_float(u3);
            *reinterpret_cast<float4*>(dst + q * 4) = v;
        }
    }
}

// ---------------- K5b: per-channel sum/sumsq of h (single pass) ----------------
__global__ void __launch_bounds__(256) k5b_reduce_h(const float* __restrict__ h) {
    int cp  = threadIdx.x & 31;
    int grp = threadIdx.x >> 5;
    int r0 = blockIdx.x * 32 + grp * 4;
    float2 y[4];
#pragma unroll
    for (int j = 0; j < 4; j++) {
        int rr = r0 + j;
        y[j] = (rr < NN) ? *reinterpret_cast<const float2*>(h + (size_t)rr * CC + 2 * cp)
                         : make_float2(0.f, 0.f);
    }
    float s1x = 0.f, s1y = 0.f, s2x = 0.f, s2y = 0.f;
#pragma unroll
    for (int j = 0; j < 4; j++) {
        s1x += y[j].x; s1y += y[j].y;
        s2x += y[j].x * y[j].x; s2y += y[j].y * y[j].y;
    }
    __shared__ float sm[4][8][32];
    sm[0][grp][cp] = s1x; sm[1][grp][cp] = s1y;
    sm[2][grp][cp] = s2x; sm[3][grp][cp] = s2y;
    __syncthreads();
    if (grp < 4) {
        float a = 0.f;
#pragma unroll
        for (int j = 0; j < 8; j++) a += sm[grp][j][cp];
        float* tgt = (grp < 2) ? g_hsum : g_hsq;
        atomicAdd(&tgt[2 * cp + (grp & 1)], a);
    }
}

// ---------------- K6: final-BN coefficients ------------------------------------
__global__ void k6_final_coeffs(const float* __restrict__ gamma,
                                const float* __restrict__ beta) {
    int c = threadIdx.x;
    float invN = 1.0f / (float)NN;
    float mean = g_hsum[c] * invN;
    float var = g_hsq[c] * invN - mean * mean;
    float a = gamma[c] * rsqrtf(var + BN_EPS);
    g_a2[c] = a;
    g_b2[c] = beta[c] - a * mean;
}

// ---------------- K7: out = relu(a2*out + b2), in place -------------------------
__global__ void k7_epilogue(float* __restrict__ out) {
    int i = blockIdx.x * blockDim.x + threadIdx.x;
    int stride = gridDim.x * blockDim.x;
    float4* ov = reinterpret_cast<float4*>(out);
    for (int q = i; q < NN * 16; q += stride) {
        int c4 = (q & 15) * 4;
        float4 h = ov[q];
        float4 r;
        r.x = fmaxf(0.f, fmaf(g_a2[c4 + 0], h.x, g_b2[c4 + 0]));
        r.y = fmaxf(0.f, fmaf(g_a2[c4 + 1], h.y, g_b2[c4 + 1]));
        r.z = fmaxf(0.f, fmaf(g_a2[c4 + 2], h.z, g_b2[c4 + 2]));
        r.w = fmaxf(0.f, fmaf(g_a2[c4 + 3], h.w, g_b2[c4 + 3]));
        ov[q] = r;
    }
}

// ---------------- launch ---------------------------------------------------------
extern "C" void kernel_launch(void* const* d_in, const int* in_sizes, int n_in,
                              void* d_out, int out_size) {
    const float* x     = (const float*)d_in[0];
    const int*   ei    = (const int*)d_in[1];
    const float* ew    = (const float*)d_in[2];
    const float* pW    = (const float*)d_in[3];
    const float* pb    = (const float*)d_in[4];
    const float* pg    = (const float*)d_in[5];
    const float* pbeta = (const float*)d_in[6];
    const float* fW    = (const float*)d_in[7];
    const float* fb    = (const float*)d_in[8];
    const float* fg    = (const float*)d_in[9];
    const float* fbeta = (const float*)d_in[10];
    const float* coef  = (const float*)d_in[11];
    float* out = (float*)d_out;

    const int rowBlocks = (NN + 127) / 128;   // 391
    k0_zero<<<1024, 256>>>();
    k1_edge_stats<<<(EE + 255) / 256, 256>>>(ei, ew, coef);
    k2_xw<<<rowBlocks, 64>>>(x, pW);
    k2b_reduce_Y<<<(NN + 31) / 32, 256>>>();
    k3_pool_coeffs<<<1, 64>>>(pb, pg, pbeta);
    k4_scatter<<<1184, 256>>>(ei, ew, coef);
    k5_final<<<rowBlocks, 64>>>(x, fW, fb, out);
    k5b_reduce_h<<<(NN + 31) / 32, 256>>>(out);
    k6_final_coeffs<<<1, 64>>>(fg, fbeta);
    k7_epilogue<<<1024, 256>>>(out);
}

// round 5
// speedup vs baseline: 1.9680x; 1.1923x over previous
#include <cuda_runtime.h>

#define NN 50000
#define EE 800000
#define CC 64
#define BN_EPS 1e-5f

// ---------------- packed f32x2 helpers (Blackwell sm_103a) -------------------
#define PACK_DUP2(out, f) \
    asm("mov.b64 %0, {%1, %1};" : "=l"(out) : "r"(__float_as_uint(f)))
#define PACK2(out, f0, f1) \
    asm("mov.b64 %0, {%1, %2};" : "=l"(out) : "r"(__float_as_uint(f0)), "r"(__float_as_uint(f1)))
#define FMA2(d, a, b) \
    asm("fma.rn.f32x2 %0, %1, %2, %0;" : "+l"(d) : "l"(a), "l"(b))
#define UNPACK2(lo, hi, v) \
    asm("mov.b64 {%0, %1}, %2;" : "=r"(lo), "=r"(hi) : "l"(v))

// ---------------- scratch (static device arrays; no allocation) -------------
__device__ float2   g_cs[NN];        // (sum s, sum s^2) per src node
__device__ float    g_S1[CC];
__device__ float    g_S2[CC];
__device__ float    g_hsum[CC];
__device__ float    g_hsq[CC];
__device__ float    g_Y[NN * CC];    // X @ pool_W
__device__ float    g_aggf[NN * CC]; // scatter-max result (>= 0)

// ---------------- K0: zero per-replay state ----------------------------------
__global__ void k0_zero() {
    int i = blockIdx.x * blockDim.x + threadIdx.x;
    int stride = gridDim.x * blockDim.x;
    float4 z = make_float4(0.f, 0.f, 0.f, 0.f);
    float4* a4 = reinterpret_cast<float4*>(g_aggf);
    for (int idx = i; idx < NN * CC / 4; idx += stride) a4[idx] = z;
    for (int idx = i; idx < NN; idx += stride) g_cs[idx] = make_float2(0.f, 0.f);
    if (i < CC) { g_S1[i] = 0.f; g_S2[i] = 0.f; g_hsum[i] = 0.f; g_hsq[i] = 0.f; }
}

// ---------------- K1: per-src sums of s, s^2 ----------------------------------
__global__ void k1_edge_stats(const int* __restrict__ ei,
                              const float* __restrict__ ew,
                              const float* __restrict__ coefp) {
    int e = blockIdx.x * blockDim.x + threadIdx.x;
    if (e >= EE) return;
    float coef = __ldg(coefp);
    int src = ei[e];
    float s = fmaf(coef, ew[e], 1.0f);
    atomicAdd(&g_cs[src].x, s);
    atomicAdd(&g_cs[src].y, s * s);
}

// ---------------- K2: Y = X @ pool_W  + fused BN-stat reduction ---------------
// 64 threads (2 warps). Warp w = column-half w of rows [b*128 + lane + 32j].
__global__ void __launch_bounds__(64) k2_xw(const float* __restrict__ x,
                                            const float* __restrict__ W) {
    __shared__ float Ws[CC * CC];   // 16 KB; reused as reduction buffer
    for (int i = threadIdx.x; i < CC * CC; i += 64) Ws[i] = W[i];
    __syncthreads();
    int half = threadIdx.x >> 5;
    int lane = threadIdx.x & 31;
    int rbase = blockIdx.x * 128 + lane;
    int r[4]; bool ok[4];
#pragma unroll
    for (int j = 0; j < 4; j++) { r[j] = rbase + 32 * j; ok[j] = r[j] < NN; }

    unsigned long long acc[4][16];
#pragma unroll
    for (int j = 0; j < 4; j++)
#pragma unroll
        for (int p = 0; p < 16; p++) acc[j][p] = 0ull;

    const float4 z4 = make_float4(0.f, 0.f, 0.f, 0.f);
#pragma unroll 4
    for (int k4 = 0; k4 < 16; k4++) {
        float4 xv[4];
#pragma unroll
        for (int j = 0; j < 4; j++)
            xv[j] = ok[j] ? *reinterpret_cast<const float4*>(
                                x + (size_t)r[j] * CC + k4 * 4)
                          : z4;
        float xk[4][4];
#pragma unroll
        for (int j = 0; j < 4; j++) {
            xk[j][0] = xv[j].x; xk[j][1] = xv[j].y;
            xk[j][2] = xv[j].z; xk[j][3] = xv[j].w;
        }
#pragma unroll
        for (int kk = 0; kk < 4; kk++) {
            unsigned long long a[4];
#pragma unroll
            for (int j = 0; j < 4; j++) PACK_DUP2(a[j], xk[j][kk]);
            const ulonglong2* wr = reinterpret_cast<const ulonglong2*>(
                &Ws[(k4 * 4 + kk) * CC + half * 32]);
#pragma unroll
            for (int p = 0; p < 8; p++) {
                ulonglong2 w = wr[p];
#pragma unroll
                for (int j = 0; j < 4; j++) {
                    FMA2(acc[j][2 * p],     a[j], w.x);
                    FMA2(acc[j][2 * p + 1], a[j], w.y);
                }
            }
        }
    }

    // epilogue: store Y and accumulate BN-stat partials
    float2 cs[4];
#pragma unroll
    for (int j = 0; j < 4; j++)
        cs[j] = ok[j] ? g_cs[r[j]] : make_float2(0.f, 0.f);
    float p1[32], p2[32];
#pragma unroll
    for (int c = 0; c < 32; c++) { p1[c] = 0.f; p2[c] = 0.f; }
#pragma unroll
    for (int j = 0; j < 4; j++) {
        float yv[32];
#pragma unroll
        for (int p = 0; p < 16; p++) {
            unsigned u0, u1;
            UNPACK2(u0, u1, acc[j][p]);
            yv[2 * p]     = __uint_as_float(u0);
            yv[2 * p + 1] = __uint_as_float(u1);
        }
        if (ok[j]) {
            float* dst = g_Y + (size_t)r[j] * CC + half * 32;
#pragma unroll
            for (int q = 0; q < 8; q++) {
                float4 v;
                v.x = yv[4 * q]; v.y = yv[4 * q + 1];
                v.z = yv[4 * q + 2]; v.w = yv[4 * q + 3];
                *reinterpret_cast<float4*>(dst + q * 4) = v;
            }
        }
#pragma unroll
        for (int c = 0; c < 32; c++) {
            p1[c] += cs[j].x * yv[c];
            p2[c] += cs[j].y * yv[c] * yv[c];
        }
    }
    // block reduction through smem (Ws is dead now)
    __syncthreads();
    float* red = Ws + half * 2048;   // per-warp region: 32 lanes x 64 floats
#pragma unroll
    for (int c = 0; c < 32; c++) {
        red[lane * 64 + c]      = p1[c];
        red[lane * 64 + 32 + c] = p2[c];
    }
    __syncwarp();
    float a = 0.f, b = 0.f;
#pragma unroll
    for (int k = 0; k < 32; k++) {
        a += red[k * 64 + lane];
        b += red[k * 64 + 32 + lane];
    }
    atomicAdd(&g_S1[half * 32 + lane], a);
    atomicAdd(&g_S2[half * 32 + lane], b);
}

// ---------------- K4: filtered scatter-max (pool-BN coeffs fused in) ----------
__global__ void __launch_bounds__(256) k4_scatter(const int* __restrict__ ei,
                                                  const float* __restrict__ ew,
                                                  const float* __restrict__ coefp,
                                                  const float* __restrict__ pb,
                                                  const float* __restrict__ gamma,
                                                  const float* __restrict__ beta) {
    __shared__ float s_al[CC], s_de[CC];
    if (threadIdx.x < CC) {
        int c = threadIdx.x;
        float invE = 1.0f / (float)EE;
        float bb = pb[c];
        float mean = g_S1[c] * invE + bb;
        float msq = (g_S2[c] + 2.f * bb * g_S1[c]) * invE + bb * bb;
        float var = msq - mean * mean;
        float alpha = gamma[c] * rsqrtf(var + BN_EPS);
        s_al[c] = alpha;
        s_de[c] = beta[c] + alpha * (bb - mean);
    }
    __syncthreads();
    float coef = __ldg(coefp);
    int lane = threadIdx.x & 31;
    int warp = (blockIdx.x * blockDim.x + threadIdx.x) >> 5;
    int nwarps = (gridDim.x * blockDim.x) >> 5;
    float al0 = s_al[2 * lane], al1 = s_al[2 * lane + 1];
    float de0 = s_de[2 * lane], de1 = s_de[2 * lane + 1];
    for (int base = warp * 32; base < EE; base += nwarps * 32) {
        int e = base + lane;
        int src = 0, dst = 0; float s = 0.f;
        if (e < EE) {
            src = ei[e];
            dst = ei[EE + e];
            s = fmaf(coef, ew[e], 1.0f);
        }
        int cnt = min(32, EE - base);
#pragma unroll 4
        for (int i = 0; i < cnt; i++) {
            int   sI = __shfl_sync(0xffffffffu, src, i);
            int   dI = __shfl_sync(0xffffffffu, dst, i);
            float sS = __shfl_sync(0xffffffffu, s, i);
            float2 yv = *reinterpret_cast<const float2*>(
                g_Y + (size_t)sI * CC + 2 * lane);
            float v0 = fmaf(al0 * sS, yv.x, de0);
            float v1 = fmaf(al1 * sS, yv.y, de1);
            float* arow = g_aggf + (size_t)dI * CC + 2 * lane;
            float2 cur = *reinterpret_cast<const float2*>(arow);
            if (v0 > cur.x)
                atomicMax(reinterpret_cast<unsigned*>(arow),     __float_as_uint(v0));
            if (v1 > cur.y)
                atomicMax(reinterpret_cast<unsigned*>(arow) + 1, __float_as_uint(v1));
        }
    }
}

// ---------------- K5: h = [x, agg] @ final_W + b (f32x2) + fused h-stats -------
__global__ void __launch_bounds__(64) k5_final(const float* __restrict__ x,
                                               const float* __restrict__ Wf,
                                               const float* __restrict__ fb,
                                               float* __restrict__ hout) {
    __shared__ float Ws[2 * CC * CC];   // 32 KB; front 16 KB reused for reduction
    for (int i = threadIdx.x; i < 2 * CC * CC; i += 64) Ws[i] = Wf[i];
    __syncthreads();
    int half = threadIdx.x >> 5;
    int lane = threadIdx.x & 31;
    int rbase = blockIdx.x * 128 + lane;
    int r[4]; bool ok[4];
#pragma unroll
    for (int j = 0; j < 4; j++) { r[j] = rbase + 32 * j; ok[j] = r[j] < NN; }

    unsigned long long acc[4][16];
    {
        const float* fbh = fb + half * 32;
        unsigned long long binit[16];
#pragma unroll
        for (int p = 0; p < 16; p++) PACK2(binit[p], fbh[2 * p], fbh[2 * p + 1]);
#pragma unroll
        for (int j = 0; j < 4; j++)
#pragma unroll
            for (int p = 0; p < 16; p++) acc[j][p] = binit[p];
    }

    const float4 z4 = make_float4(0.f, 0.f, 0.f, 0.f);
#pragma unroll
    for (int ph = 0; ph < 2; ph++) {
        const float* src = (ph == 0) ? x : g_aggf;
        const float* Wb  = Ws + ph * CC * CC;
#pragma unroll 4
        for (int k4 = 0; k4 < 16; k4++) {
            float4 xv[4];
#pragma unroll
            for (int j = 0; j < 4; j++)
                xv[j] = ok[j] ? *reinterpret_cast<const float4*>(
                                    src + (size_t)r[j] * CC + k4 * 4)
                              : z4;
            float xk[4][4];
#pragma unroll
            for (int j = 0; j < 4; j++) {
                xk[j][0] = xv[j].x; xk[j][1] = xv[j].y;
                xk[j][2] = xv[j].z; xk[j][3] = xv[j].w;
            }
#pragma unroll
            for (int kk = 0; kk < 4; kk++) {
                unsigned long long a[4];
#pragma unroll
                for (int j = 0; j < 4; j++) PACK_DUP2(a[j], xk[j][kk]);
                const ulonglong2* wr = reinterpret_cast<const ulonglong2*>(
                    &Wb[(k4 * 4 + kk) * CC + half * 32]);
#pragma unroll
                for (int p = 0; p < 8; p++) {
                    ulonglong2 w = wr[p];
#pragma unroll
                    for (int j = 0; j < 4; j++) {
                        FMA2(acc[j][2 * p],     a[j], w.x);
                        FMA2(acc[j][2 * p + 1], a[j], w.y);
                    }
                }
            }
        }
    }

    // epilogue: store h + accumulate per-channel sum / sumsq
    float p1[32], p2[32];
#pragma unroll
    for (int c = 0; c < 32; c++) { p1[c] = 0.f; p2[c] = 0.f; }
#pragma unroll
    for (int j = 0; j < 4; j++) {
        float hv[32];
#pragma unroll
        for (int p = 0; p < 16; p++) {
            unsigned u0, u1;
            UNPACK2(u0, u1, acc[j][p]);
            hv[2 * p]     = __uint_as_float(u0);
            hv[2 * p + 1] = __uint_as_float(u1);
        }
        if (ok[j]) {
            float* dst = hout + (size_t)r[j] * CC + half * 32;
#pragma unroll
            for (int q = 0; q < 8; q++) {
                float4 v;
                v.x = hv[4 * q]; v.y = hv[4 * q + 1];
                v.z = hv[4 * q + 2]; v.w = hv[4 * q + 3];
                *reinterpret_cast<float4*>(dst + q * 4) = v;
            }
#pragma unroll
            for (int c = 0; c < 32; c++) {
                p1[c] += hv[c];
                p2[c] += hv[c] * hv[c];
            }
        }
    }
    __syncthreads();
    float* red = Ws + half * 2048;
#pragma unroll
    for (int c = 0; c < 32; c++) {
        red[lane * 64 + c]      = p1[c];
        red[lane * 64 + 32 + c] = p2[c];
    }
    __syncwarp();
    float a = 0.f, b = 0.f;
#pragma unroll
    for (int k = 0; k < 32; k++) {
        a += red[k * 64 + lane];
        b += red[k * 64 + 32 + lane];
    }
    atomicAdd(&g_hsum[half * 32 + lane], a);
    atomicAdd(&g_hsq[half * 32 + lane], b);
}

// ---------------- K7: out = relu(a2*out + b2), in place (BN coeffs fused) ------
__global__ void __launch_bounds__(256) k7_epilogue(float* __restrict__ out,
                                                   const float* __restrict__ gamma,
                                                   const float* __restrict__ beta) {
    __shared__ float s_a[CC], s_b[CC];
    if (threadIdx.x < CC) {
        int c = threadIdx.x;
        float invN = 1.0f / (float)NN;
        float mean = g_hsum[c] * invN;
        float var = g_hsq[c] * invN - mean * mean;
        float a = gamma[c] * rsqrtf(var + BN_EPS);
        s_a[c] = a;
        s_b[c] = beta[c] - a * mean;
    }
    __syncthreads();
    int i = blockIdx.x * blockDim.x + threadIdx.x;
    int stride = gridDim.x * blockDim.x;
    float4* ov = reinterpret_cast<float4*>(out);
    for (int q = i; q < NN * 16; q += stride) {
        int c4 = (q & 15) * 4;
        float4 h = ov[q];
        float4 r;
        r.x = fmaxf(0.f, fmaf(s_a[c4 + 0], h.x, s_b[c4 + 0]));
        r.y = fmaxf(0.f, fmaf(s_a[c4 + 1], h.y, s_b[c4 + 1]));
        r.z = fmaxf(0.f, fmaf(s_a[c4 + 2], h.z, s_b[c4 + 2]));
        r.w = fmaxf(0.f, fmaf(s_a[c4 + 3], h.w, s_b[c4 + 3]));
        ov[q] = r;
    }
}

// ---------------- launch ---------------------------------------------------------
extern "C" void kernel_launch(void* const* d_in, const int* in_sizes, int n_in,
                              void* d_out, int out_size) {
    const float* x     = (const float*)d_in[0];
    const int*   ei    = (const int*)d_in[1];
    const float* ew    = (const float*)d_in[2];
    const float* pW    = (const float*)d_in[3];
    const float* pb    = (const float*)d_in[4];
    const float* pg    = (const float*)d_in[5];
    const float* pbeta = (const float*)d_in[6];
    const float* fW    = (const float*)d_in[7];
    const float* fb    = (const float*)d_in[8];
    const float* fg    = (const float*)d_in[9];
    const float* fbeta = (const float*)d_in[10];
    const float* coef  = (const float*)d_in[11];
    float* out = (float*)d_out;

    const int rowBlocks = (NN + 127) / 128;   // 391
    k0_zero<<<1024, 256>>>();
    k1_edge_stats<<<(EE + 255) / 256, 256>>>(ei, ew, coef);
    k2_xw<<<rowBlocks, 64>>>(x, pW);
    k4_scatter<<<1184, 256>>>(ei, ew, coef, pb, pg, pbeta);
    k5_final<<<rowBlocks, 64>>>(x, fW, fb, out);
    k7_epilogue<<<1024, 256>>>(out, fg, fbeta);
}

// round 6
// speedup vs baseline: 2.0265x; 1.0297x over previous
#include <cuda_runtime.h>
#include <cuda_fp16.h>

#define NN 50000
#define EE 800000
#define CC 64
#define BN_EPS 1e-5f

// ---------------- packed f32x2 helpers (Blackwell sm_103a) -------------------
#define PACK_DUP2(out, f) \
    asm("mov.b64 %0, {%1, %1};" : "=l"(out) : "r"(__float_as_uint(f)))
#define PACK2(out, f0, f1) \
    asm("mov.b64 %0, {%1, %2};" : "=l"(out) : "r"(__float_as_uint(f0)), "r"(__float_as_uint(f1)))
#define FMA2(d, a, b) \
    asm("fma.rn.f32x2 %0, %1, %2, %0;" : "+l"(d) : "l"(a), "l"(b))
#define UNPACK2(lo, hi, v) \
    asm("mov.b64 {%0, %1}, %2;" : "=r"(lo), "=r"(hi) : "l"(v))

// ---------------- scratch (static device arrays; no allocation) -------------
__device__ float2   g_cs[NN];        // (sum s, sum s^2) per src node
__device__ float    g_S1[CC];
__device__ float    g_S2[CC];
__device__ float    g_hsum[CC];
__device__ float    g_hsq[CC];
__device__ __half2  g_Yh[NN * 32];   // X @ pool_W, fp16x2 (k4 gather only)
__device__ float    g_aggf[NN * CC]; // scatter-max result (>= 0)

// ---------------- K0: zero small per-replay state -----------------------------
__global__ void k0_zero() {
    int i = blockIdx.x * blockDim.x + threadIdx.x;
    if (i < NN) g_cs[i] = make_float2(0.f, 0.f);
    if (i < CC) { g_S1[i] = 0.f; g_S2[i] = 0.f; g_hsum[i] = 0.f; g_hsq[i] = 0.f; }
}

// ---------------- K1: per-src sums of s, s^2 + zero agg ------------------------
__global__ void k1_edge_stats(const int* __restrict__ ei,
                              const float* __restrict__ ew,
                              const float* __restrict__ coefp) {
    int i = blockIdx.x * blockDim.x + threadIdx.x;
    int stride = gridDim.x * blockDim.x;
    // zero scatter-max target (safe: k1 atomics touch only g_cs; k4 runs later)
    float4 z = make_float4(0.f, 0.f, 0.f, 0.f);
    float4* a4 = reinterpret_cast<float4*>(g_aggf);
    for (int idx = i; idx < NN * CC / 4; idx += stride) a4[idx] = z;
    if (i >= EE) return;
    float coef = __ldg(coefp);
    int src = ei[i];
    float s = fmaf(coef, ew[i], 1.0f);
    atomicAdd(&g_cs[src].x, s);
    atomicAdd(&g_cs[src].y, s * s);
}

// ---------------- K2: Y = X @ pool_W (f32x2) + fused BN-stats, fp16 Y out -----
// 64 threads (2 warps). Warp w = column-half w of rows [b*128 + lane + 32j].
__global__ void __launch_bounds__(64) k2_xw(const float* __restrict__ x,
                                            const float* __restrict__ W) {
    __shared__ float Ws[CC * CC];   // 16 KB; reused as reduction buffer
    for (int i = threadIdx.x; i < CC * CC; i += 64) Ws[i] = W[i];
    __syncthreads();
    int half = threadIdx.x >> 5;
    int lane = threadIdx.x & 31;
    int rbase = blockIdx.x * 128 + lane;
    int r[4]; bool ok[4];
#pragma unroll
    for (int j = 0; j < 4; j++) { r[j] = rbase + 32 * j; ok[j] = r[j] < NN; }

    unsigned long long acc[4][16];
#pragma unroll
    for (int j = 0; j < 4; j++)
#pragma unroll
        for (int p = 0; p < 16; p++) acc[j][p] = 0ull;

    const float4 z4 = make_float4(0.f, 0.f, 0.f, 0.f);
#pragma unroll 4
    for (int k4 = 0; k4 < 16; k4++) {
        float4 xv[4];
#pragma unroll
        for (int j = 0; j < 4; j++)
            xv[j] = ok[j] ? *reinterpret_cast<const float4*>(
                                x + (size_t)r[j] * CC + k4 * 4)
                          : z4;
        float xk[4][4];
#pragma unroll
        for (int j = 0; j < 4; j++) {
            xk[j][0] = xv[j].x; xk[j][1] = xv[j].y;
            xk[j][2] = xv[j].z; xk[j][3] = xv[j].w;
        }
#pragma unroll
        for (int kk = 0; kk < 4; kk++) {
            unsigned long long a[4];
#pragma unroll
            for (int j = 0; j < 4; j++) PACK_DUP2(a[j], xk[j][kk]);
            const ulonglong2* wr = reinterpret_cast<const ulonglong2*>(
                &Ws[(k4 * 4 + kk) * CC + half * 32]);
#pragma unroll
            for (int p = 0; p < 8; p++) {
                ulonglong2 w = wr[p];
#pragma unroll
                for (int j = 0; j < 4; j++) {
                    FMA2(acc[j][2 * p],     a[j], w.x);
                    FMA2(acc[j][2 * p + 1], a[j], w.y);
                }
            }
        }
    }

    // epilogue: store Y (fp16) and accumulate BN-stat partials (fp32)
    float2 cs[4];
#pragma unroll
    for (int j = 0; j < 4; j++)
        cs[j] = ok[j] ? g_cs[r[j]] : make_float2(0.f, 0.f);
    float p1[32], p2[32];
#pragma unroll
    for (int c = 0; c < 32; c++) { p1[c] = 0.f; p2[c] = 0.f; }
#pragma unroll
    for (int j = 0; j < 4; j++) {
        float yv[32];
#pragma unroll
        for (int p = 0; p < 16; p++) {
            unsigned u0, u1;
            UNPACK2(u0, u1, acc[j][p]);
            yv[2 * p]     = __uint_as_float(u0);
            yv[2 * p + 1] = __uint_as_float(u1);
        }
        if (ok[j]) {
            __half2 hh[16];
#pragma unroll
            for (int c2 = 0; c2 < 16; c2++)
                hh[c2] = __floats2half2_rn(yv[2 * c2], yv[2 * c2 + 1]);
            uint4* dst = reinterpret_cast<uint4*>(g_Yh + (size_t)r[j] * 32 + half * 16);
            const uint4* srcv = reinterpret_cast<const uint4*>(hh);
#pragma unroll
            for (int q = 0; q < 4; q++) dst[q] = srcv[q];
        }
#pragma unroll
        for (int c = 0; c < 32; c++) {
            p1[c] += cs[j].x * yv[c];
            p2[c] += cs[j].y * yv[c] * yv[c];
        }
    }
    // block reduction through smem (Ws is dead now)
    __syncthreads();
    float* red = Ws + half * 2048;   // per-warp region: 32 lanes x 64 floats
#pragma unroll
    for (int c = 0; c < 32; c++) {
        red[lane * 64 + c]      = p1[c];
        red[lane * 64 + 32 + c] = p2[c];
    }
    __syncwarp();
    float a = 0.f, b = 0.f;
#pragma unroll
    for (int k = 0; k < 32; k++) {
        a += red[k * 64 + lane];
        b += red[k * 64 + 32 + lane];
    }
    atomicAdd(&g_S1[half * 32 + lane], a);
    atomicAdd(&g_S2[half * 32 + lane], b);
}

// ---------------- K4: filtered scatter-max (pool-BN coeffs fused in) ----------
__global__ void __launch_bounds__(256) k4_scatter(const int* __restrict__ ei,
                                                  const float* __restrict__ ew,
                                                  const float* __restrict__ coefp,
                                                  const float* __restrict__ pb,
                                                  const float* __restrict__ gamma,
                                                  const float* __restrict__ beta) {
    __shared__ float s_al[CC], s_de[CC];
    if (threadIdx.x < CC) {
        int c = threadIdx.x;
        float invE = 1.0f / (float)EE;
        float bb = pb[c];
        float mean = g_S1[c] * invE + bb;
        float msq = (g_S2[c] + 2.f * bb * g_S1[c]) * invE + bb * bb;
        float var = msq - mean * mean;
        float alpha = gamma[c] * rsqrtf(var + BN_EPS);
        s_al[c] = alpha;
        s_de[c] = beta[c] + alpha * (bb - mean);
    }
    __syncthreads();
    float coef = __ldg(coefp);
    int lane = threadIdx.x & 31;
    int warp = (blockIdx.x * blockDim.x + threadIdx.x) >> 5;
    int nwarps = (gridDim.x * blockDim.x) >> 5;
    float al0 = s_al[2 * lane], al1 = s_al[2 * lane + 1];
    float de0 = s_de[2 * lane], de1 = s_de[2 * lane + 1];
    for (int base = warp * 32; base < EE; base += nwarps * 32) {
        int e = base + lane;
        int src = 0, dst = 0; float s = 0.f;
        if (e < EE) {
            src = ei[e];
            dst = ei[EE + e];
            s = fmaf(coef, ew[e], 1.0f);
        }
        int cnt = min(32, EE - base);
#pragma unroll 4
        for (int i = 0; i < cnt; i++) {
            int   sI = __shfl_sync(0xffffffffu, src, i);
            int   dI = __shfl_sync(0xffffffffu, dst, i);
            float sS = __shfl_sync(0xffffffffu, s, i);
            __half2 yh = __ldg(g_Yh + (size_t)sI * 32 + lane);
            float2 yv = __half22float2(yh);
            float v0 = fmaf(al0 * sS, yv.x, de0);
            float v1 = fmaf(al1 * sS, yv.y, de1);
            float* arow = g_aggf + (size_t)dI * CC + 2 * lane;
            float2 cur = *reinterpret_cast<const float2*>(arow);
            if (v0 > cur.x)
                atomicMax(reinterpret_cast<unsigned*>(arow),     __float_as_uint(v0));
            if (v1 > cur.y)
                atomicMax(reinterpret_cast<unsigned*>(arow) + 1, __float_as_uint(v1));
        }
    }
}

// ---------------- K5: h = [x, agg] @ final_W + b (f32x2) + fused h-stats -------
__global__ void __launch_bounds__(64) k5_final(const float* __restrict__ x,
                                               const float* __restrict__ Wf,
                                               const float* __restrict__ fb,
                                               float* __restrict__ hout) {
    __shared__ float Ws[2 * CC * CC];   // 32 KB; front 16 KB reused for reduction
    for (int i = threadIdx.x; i < 2 * CC * CC; i += 64) Ws[i] = Wf[i];
    __syncthreads();
    int half = threadIdx.x >> 5;
    int lane = threadIdx.x & 31;
    int rbase = blockIdx.x * 128 + lane;
    int r[4]; bool ok[4];
#pragma unroll
    for (int j = 0; j < 4; j++) { r[j] = rbase + 32 * j; ok[j] = r[j] < NN; }

    unsigned long long acc[4][16];
    {
        const float* fbh = fb + half * 32;
        unsigned long long binit[16];
#pragma unroll
        for (int p = 0; p < 16; p++) PACK2(binit[p], fbh[2 * p], fbh[2 * p + 1]);
#pragma unroll
        for (int j = 0; j < 4; j++)
#pragma unroll
            for (int p = 0; p < 16; p++) acc[j][p] = binit[p];
    }

    const float4 z4 = make_float4(0.f, 0.f, 0.f, 0.f);
#pragma unroll
    for (int ph = 0; ph < 2; ph++) {
        const float* src = (ph == 0) ? x : g_aggf;
        const float* Wb  = Ws + ph * CC * CC;
#pragma unroll 4
        for (int k4 = 0; k4 < 16; k4++) {
            float4 xv[4];
#pragma unroll
            for (int j = 0; j < 4; j++)
                xv[j] = ok[j] ? *reinterpret_cast<const float4*>(
                                    src + (size_t)r[j] * CC + k4 * 4)
                              : z4;
            float xk[4][4];
#pragma unroll
            for (int j = 0; j < 4; j++) {
                xk[j][0] = xv[j].x; xk[j][1] = xv[j].y;
                xk[j][2] = xv[j].z; xk[j][3] = xv[j].w;
            }
#pragma unroll
            for (int kk = 0; kk < 4; kk++) {
                unsigned long long a[4];
#pragma unroll
                for (int j = 0; j < 4; j++) PACK_DUP2(a[j], xk[j][kk]);
                const ulonglong2* wr = reinterpret_cast<const ulonglong2*>(
                    &Wb[(k4 * 4 + kk) * CC + half * 32]);
#pragma unroll
                for (int p = 0; p < 8; p++) {
                    ulonglong2 w = wr[p];
#pragma unroll
                    for (int j = 0; j < 4; j++) {
                        FMA2(acc[j][2 * p],     a[j], w.x);
                        FMA2(acc[j][2 * p + 1], a[j], w.y);
                    }
                }
            }
        }
    }

    // epilogue: store h + accumulate per-channel sum / sumsq
    float p1[32], p2[32];
#pragma unroll
    for (int c = 0; c < 32; c++) { p1[c] = 0.f; p2[c] = 0.f; }
#pragma unroll
    for (int j = 0; j < 4; j++) {
        float hv[32];
#pragma unroll
        for (int p = 0; p < 16; p++) {
            unsigned u0, u1;
            UNPACK2(u0, u1, acc[j][p]);
            hv[2 * p]     = __uint_as_float(u0);
            hv[2 * p + 1] = __uint_as_float(u1);
        }
        if (ok[j]) {
            float* dst = hout + (size_t)r[j] * CC + half * 32;
#pragma unroll
            for (int q = 0; q < 8; q++) {
                float4 v;
                v.x = hv[4 * q]; v.y = hv[4 * q + 1];
                v.z = hv[4 * q + 2]; v.w = hv[4 * q + 3];
                *reinterpret_cast<float4*>(dst + q * 4) = v;
            }
#pragma unroll
            for (int c = 0; c < 32; c++) {
                p1[c] += hv[c];
                p2[c] += hv[c] * hv[c];
            }
        }
    }
    __syncthreads();
    float* red = Ws + half * 2048;
#pragma unroll
    for (int c = 0; c < 32; c++) {
        red[lane * 64 + c]      = p1[c];
        red[lane * 64 + 32 + c] = p2[c];
    }
    __syncwarp();
    float a = 0.f, b = 0.f;
#pragma unroll
    for (int k = 0; k < 32; k++) {
        a += red[k * 64 + lane];
        b += red[k * 64 + 32 + lane];
    }
    atomicAdd(&g_hsum[half * 32 + lane], a);
    atomicAdd(&g_hsq[half * 32 + lane], b);
}

// ---------------- K7: out = relu(a2*out + b2), in place (BN coeffs fused) ------
__global__ void __launch_bounds__(256) k7_epilogue(float* __restrict__ out,
                                                   const float* __restrict__ gamma,
                                                   const float* __restrict__ beta) {
    __shared__ float s_a[CC], s_b[CC];
    if (threadIdx.x < CC) {
        int c = threadIdx.x;
        float invN = 1.0f / (float)NN;
        float mean = g_hsum[c] * invN;
        float var = g_hsq[c] * invN - mean * mean;
        float a = gamma[c] * rsqrtf(var + BN_EPS);
        s_a[c] = a;
        s_b[c] = beta[c] - a * mean;
    }
    __syncthreads();
    int i = blockIdx.x * blockDim.x + threadIdx.x;
    int stride = gridDim.x * blockDim.x;
    float4* ov = reinterpret_cast<float4*>(out);
    for (int q = i; q < NN * 16; q += stride) {
        int c4 = (q & 15) * 4;
        float4 h = ov[q];
        float4 r;
        r.x = fmaxf(0.f, fmaf(s_a[c4 + 0], h.x, s_b[c4 + 0]));
        r.y = fmaxf(0.f, fmaf(s_a[c4 + 1], h.y, s_b[c4 + 1]));
        r.z = fmaxf(0.f, fmaf(s_a[c4 + 2], h.z, s_b[c4 + 2]));
        r.w = fmaxf(0.f, fmaf(s_a[c4 + 3], h.w, s_b[c4 + 3]));
        ov[q] = r;
    }
}

// ---------------- launch ---------------------------------------------------------
extern "C" void kernel_launch(void* const* d_in, const int* in_sizes, int n_in,
                              void* d_out, int out_size) {
    const float* x     = (const float*)d_in[0];
    const int*   ei    = (const int*)d_in[1];
    const float* ew    = (const float*)d_in[2];
    const float* pW    = (const float*)d_in[3];
    const float* pb    = (const float*)d_in[4];
    const float* pg    = (const float*)d_in[5];
    const float* pbeta = (const float*)d_in[6];
    const float* fW    = (const float*)d_in[7];
    const float* fb    = (const float*)d_in[8];
    const float* fg    = (const float*)d_in[9];
    const float* fbeta = (const float*)d_in[10];
    const float* coef  = (const float*)d_in[11];
    float* out = (float*)d_out;

    const int rowBlocks = (NN + 127) / 128;   // 391
    k0_zero<<<(NN + 255) / 256, 256>>>();
    k1_edge_stats<<<(EE + 255) / 256, 256>>>(ei, ew, coef);
    k2_xw<<<rowBlocks, 64>>>(x, pW);
    k4_scatter<<<1184, 256>>>(ei, ew, coef, pb, pg, pbeta);
    k5_final<<<rowBlocks, 64>>>(x, fW, fb, out);
    k7_epilogue<<<1024, 256>>>(out, fg, fbeta);
}